// round 15
// baseline (speedup 1.0000x reference)
#include <cuda_runtime.h>

// Reverse (suffix) cumulative sum along dim=1.
// x: (2048, 32768) fp32. out[b, j] = sum_{k >= j} x[b, k].
//
// FINAL (R15): converged memory-bound kernel.
//  - One CTA per row, 1024 threads. 256-bit vector ops (LDG.E.256 /
//    STG.E.256): thread holds 4 slots of 8 consecutive floats, slot i at
//    warp_base + i*256 + lane*8 -> every instruction covers 8 contiguous
//    128B lines (full-width wavefronts).
//  - Suffix scan: 3-deep TREE inside each float8 -> 4 interleaved warp
//    shfl chains -> register suffix over slots -> single-barrier block
//    scan of 32 warp totals (every warp redundantly scans, picks its own
//    offset via shfl).
//  - Default cache policy (hints/TMA/prefetch all measured slower).

#define N_COLS   32768
#define THREADS  1024
#define SLOTS    4        // float8s per thread
#define VEC      8        // floats per vector op

__global__ __launch_bounds__(THREADS, 1)
void revcumsum_kernel(const float* __restrict__ x, float* __restrict__ out) {
    const long long base = (long long)blockIdx.x * N_COLS;
    const int t    = threadIdx.x;
    const int lane = t & 31;
    const int wid  = t >> 5;

    const float* __restrict__ xin = x + base + wid * 1024 + lane * VEC;

    // ---- 256-bit coalesced loads (batched for max MLP) ----
    float v[SLOTS][VEC];
    #pragma unroll
    for (int i = 0; i < SLOTS; i++) {
        asm volatile(
            "ld.global.v8.f32 {%0,%1,%2,%3,%4,%5,%6,%7}, [%8];"
            : "=f"(v[i][0]), "=f"(v[i][1]), "=f"(v[i][2]), "=f"(v[i][3]),
              "=f"(v[i][4]), "=f"(v[i][5]), "=f"(v[i][6]), "=f"(v[i][7])
            : "l"(xin + i * 256));
    }

    // ---- suffix scan inside each float8, 3-deep tree ----
    // step 1: distance-1 pairs; step 2: distance-2; step 3: distance-4.
    float s[SLOTS];
    #pragma unroll
    for (int i = 0; i < SLOTS; i++) {
        // d=1
        v[i][6] += v[i][7];
        v[i][4] += v[i][5];
        v[i][2] += v[i][3];
        v[i][0] += v[i][1];
        // d=2
        v[i][5] += v[i][6];   // (5)+(6,7)
        v[i][4] += v[i][6];   // (4,5)+(6,7)
        v[i][1] += v[i][2];
        v[i][0] += v[i][2];
        // d=4
        v[i][3] += v[i][4];   // wait: careful ordering below
        v[i][2] += v[i][4];
        v[i][1] += v[i][4];
        v[i][0] += v[i][4];
        s[i] = v[i][0];
    }
    // Note on correctness of the tree above:
    //  after d=1: v7=x7, v6=x6+x7, v5=x5, v4=x4+x5, v3=x3, v2=x2+x3, v1=x1, v0=x0+x1
    //  after d=2: v5=x5+x6+x7, v4=x4..x7, v1=x1+x2+x3, v0=x0..x3   (v6,v2 already suffix within half)
    //  d=4 adds v4 (=x4..x7) to v0..v3 -> v3=x3+..., v2=x2+x3+x4..x7, v1=x1..x7, v0=x0..x7
    //  v3 needed x3 + (x4..x7): v3 was x3 -> += v4 OK.
    //  v2 was x2+x3 -> += v4 OK. v1 was x1+x2+x3 -> += v4 OK. v0 was x0..x3 -> += v4 OK.
    //  v5,v6,v7 already complete suffixes. All 8 correct.

    // ---- per-slot warp suffix scans (4 independent chains) ----
    float incl0 = s[0], incl1 = s[1], incl2 = s[2], incl3 = s[3];
    #pragma unroll
    for (int d = 1; d < 32; d <<= 1) {
        float a0 = __shfl_down_sync(0xFFFFFFFFu, incl0, d);
        float a1 = __shfl_down_sync(0xFFFFFFFFu, incl1, d);
        float a2 = __shfl_down_sync(0xFFFFFFFFu, incl2, d);
        float a3 = __shfl_down_sync(0xFFFFFFFFu, incl3, d);
        if (lane + d < 32) {
            incl0 += a0; incl1 += a1; incl2 += a2; incl3 += a3;
        }
    }
    float excl[SLOTS];
    excl[0] = incl0 - s[0];
    excl[1] = incl1 - s[1];
    excl[2] = incl2 - s[2];
    excl[3] = incl3 - s[3];
    float T[SLOTS];
    T[0] = __shfl_sync(0xFFFFFFFFu, incl0, 0);
    T[1] = __shfl_sync(0xFFFFFFFFu, incl1, 0);
    T[2] = __shfl_sync(0xFFFFFFFFu, incl2, 0);
    T[3] = __shfl_sync(0xFFFFFFFFu, incl3, 0);

    // ---- register suffix over slots ----
    float O[SLOTS];
    O[3] = 0.0f;
    O[2] = T[3];
    O[1] = T[3] + T[2];
    O[0] = O[1] + T[1];
    const float warp_total = O[0] + T[0];

    // ---- block suffix scan over 32 warp totals: single barrier ----
    __shared__ float warp_tot[32];
    if (lane == 0) warp_tot[wid] = warp_total;
    __syncthreads();

    float w  = warp_tot[lane];
    float iw = w;
    #pragma unroll
    for (int d = 1; d < 32; d <<= 1) {
        float tmp = __shfl_down_sync(0xFFFFFFFFu, iw, d);
        if (lane + d < 32) iw += tmp;
    }
    const float woff = __shfl_sync(0xFFFFFFFFu, iw - w, wid);

    // ---- apply offsets, 256-bit coalesced stores ----
    float* __restrict__ o = out + base + wid * 1024 + lane * VEC;
    #pragma unroll
    for (int i = 0; i < SLOTS; i++) {
        const float off = woff + O[i] + excl[i];
        float w0 = v[i][0] + off, w1 = v[i][1] + off;
        float w2 = v[i][2] + off, w3 = v[i][3] + off;
        float w4 = v[i][4] + off, w5 = v[i][5] + off;
        float w6 = v[i][6] + off, w7 = v[i][7] + off;
        asm volatile(
            "st.global.v8.f32 [%0], {%1,%2,%3,%4,%5,%6,%7,%8};"
            :: "l"(o + i * 256),
               "f"(w0), "f"(w1), "f"(w2), "f"(w3),
               "f"(w4), "f"(w5), "f"(w6), "f"(w7)
            : "memory");
    }
}

extern "C" void kernel_launch(void* const* d_in, const int* in_sizes, int n_in,
                              void* d_out, int out_size) {
    const float* x = (const float*)d_in[0];
    float* out = (float*)d_out;
    const int n    = in_sizes[0];       // B * N
    const int rows = n / N_COLS;        // 2048
    revcumsum_kernel<<<rows, THREADS>>>(x, out);
}